// round 15
// baseline (speedup 1.0000x reference)
#include <cuda_runtime.h>
#include <cstdint>

#define LOG2E     1.4426950408889634f
#define TWO_LOG2E 2.8853900817779268f

// ---------------- scratch (device globals: no allocation allowed) ----------
__device__ float g_gi[2400 * 768];   // pre-GRU input gates  [t*8+n][768]
__device__ float g_u2[1280 * 256];   // 2*log2e * (memory @ U^T)  [n*160+x][256]
__device__ float g_w2[2400 * 256];   // 2*log2e * (outputs @ W^T) [n*300+t][256]

// ---------------- fast math ------------------------------------------------
__device__ __forceinline__ float ex2f_(float x) {
    float y; asm("ex2.approx.f32 %0, %1;" : "=f"(y) : "f"(x)); return y;
}
__device__ __forceinline__ float rcpf_(float x) {
    float y; asm("rcp.approx.f32 %0, %1;" : "=f"(y) : "f"(x)); return y;
}
__device__ __forceinline__ float sigmoidf_(float x) {
    return rcpf_(1.f + ex2f_(-x * LOG2E));
}
__device__ __forceinline__ float tanhf_(float x) {
    return fmaf(-2.f, rcpf_(1.f + ex2f_(x * TWO_LOG2E)), 1.f);
}
__device__ __forceinline__ unsigned smem_u32_(const void* p) {
    unsigned a;
    asm("{ .reg .u64 t; cvta.to.shared.u64 t, %1; cvt.u32.u64 %0, t; }"
        : "=r"(a) : "l"(p));
    return a;
}
__device__ __forceinline__ unsigned long long fma2_(unsigned long long a,
                                                    unsigned long long b,
                                                    unsigned long long c) {
    unsigned long long d;
    asm("fma.rn.f32x2 %0, %1, %2, %3;" : "=l"(d) : "l"(a), "l"(b), "l"(c));
    return d;
}

// ---------------- kernel A: gi = inputs @ Wih^T + bih (+bhh for r,z) -------
__global__ void gi_kernel(const float* __restrict__ inp,
                          const float* __restrict__ Wih,
                          const float* __restrict__ bih,
                          const float* __restrict__ bhh) {
    __shared__ float xs[16][128];
    int tid = threadIdx.x;
    int ib = blockIdx.x, jb = blockIdx.y;
    int j = jb * 256 + tid;

    for (int q = 0; q < 2; q++) {
        int f4 = tid + 256 * q;
        int ii = f4 >> 5, pos = f4 & 31;
        int i = ib * 16 + ii;
        int t = i >> 3, n = i & 7;
        ((float4*)xs[ii])[pos] = ((const float4*)(inp + (n * 300 + t) * 128))[pos];
    }
    __syncthreads();

    float acc[16];
#pragma unroll
    for (int ii = 0; ii < 16; ii++) acc[ii] = 0.f;

    const float4* wr = (const float4*)(Wih + (size_t)j * 128);
    for (int k4 = 0; k4 < 32; k4++) {
        float4 w4 = __ldg(wr + k4);
#pragma unroll
        for (int ii = 0; ii < 16; ii++) {
            float4 xv = ((const float4*)xs[ii])[k4];
            acc[ii] = fmaf(w4.x, xv.x, acc[ii]);
            acc[ii] = fmaf(w4.y, xv.y, acc[ii]);
            acc[ii] = fmaf(w4.z, xv.z, acc[ii]);
            acc[ii] = fmaf(w4.w, xv.w, acc[ii]);
        }
    }
    float b = bih[j] + (jb < 2 ? bhh[j] : 0.f);
#pragma unroll
    for (int ii = 0; ii < 16; ii++)
        g_gi[(size_t)(ib * 16 + ii) * 768 + j] = acc[ii] + b;
}

// ---------------- shared 256-K GEMM body (R12 version) ----------------------
__device__ __forceinline__ void gemm256_body(const float* __restrict__ A,
                                             const float* __restrict__ B,
                                             float* __restrict__ out,
                                             float scale) {
    __shared__ float xs[16][256];
    int tid = threadIdx.x, ib = blockIdx.x;
    for (int q = 0; q < 4; q++) {
        int f4 = tid + 256 * q;
        int ii = f4 >> 6, pos = f4 & 63;
        ((float4*)xs[ii])[pos] = ((const float4*)(A + (size_t)(ib * 16 + ii) * 256))[pos];
    }
    __syncthreads();

    float acc[16];
#pragma unroll
    for (int ii = 0; ii < 16; ii++) acc[ii] = 0.f;

    const float4* br = (const float4*)(B + (size_t)tid * 256);
    for (int k4 = 0; k4 < 64; k4++) {
        float4 b4 = __ldg(br + k4);
#pragma unroll
        for (int ii = 0; ii < 16; ii++) {
            float4 xv = ((const float4*)xs[ii])[k4];
            acc[ii] = fmaf(b4.x, xv.x, acc[ii]);
            acc[ii] = fmaf(b4.y, xv.y, acc[ii]);
            acc[ii] = fmaf(b4.z, xv.z, acc[ii]);
            acc[ii] = fmaf(b4.w, xv.w, acc[ii]);
        }
    }
#pragma unroll
    for (int ii = 0; ii < 16; ii++)
        out[(size_t)(ib * 16 + ii) * 256 + tid] = scale * acc[ii];
}

__global__ void u_kernel(const float* __restrict__ mem, const float* __restrict__ U) {
    gemm256_body(mem, U, g_u2, TWO_LOG2E);
}
__global__ void w_kernel(const float* __restrict__ outp, const float* __restrict__ W) {
    gemm256_body(outp, W, g_w2, TWO_LOG2E);
}

// ---------------- profiling alignment no-op (gru stays launch idx 3) -------
__global__ void probe_kernel() {}

// ---------------- GRU: 8-CTA cluster per batch; PER-SOURCE mbarriers -------
// Thread (u,c) consumes chunk c (from CTA c) and produces for CTA c ONLY.
// mbar[src][slot]: push signals peer c's mbar[r]; thread waits on LOCAL
// mbar[c]. RACE FIX vs R14: `hold` reads chunk r, whose arrival signals
// mbar[r] — waited by lane r of the SAME warp. One __syncwarp() after the
// per-lane waits creates the happens-before edge (lane-r-acquire -> warp
// barrier -> any lane's hold read).
__global__ void __launch_bounds__(256, 1) __cluster_dims__(8, 1, 1)
gru_kernel(const float* __restrict__ h0, const float* __restrict__ Whh,
           const float* __restrict__ bhh,
           float* __restrict__ outp, float* __restrict__ hid) {
    __shared__ __align__(16) float hbuf[2][288];              // 8 chunks x 36
    __shared__ __align__(8)  unsigned long long mbar[8][2];   // [src][slot]

    int tid = threadIdx.x;
    int n = blockIdx.x >> 3;
    unsigned r;
    asm("mov.u32 %0, %%cluster_ctarank;" : "=r"(r));
    int u = tid >> 3, c = tid & 7;
    const int eg = 32 * (int)r + u;

    if (tid < 16) {     // init mbar[tid>>1][tid&1], arrive count = 1 (the arm)
        unsigned m = smem_u32_(&mbar[tid >> 1][tid & 1]);
        asm volatile("mbarrier.init.shared.b64 [%0], 1;" :: "r"(m) : "memory");
    }
    hbuf[0][(tid >> 5) * 36 + (tid & 31)] = h0[n * 256 + tid];
    __syncthreads();
    asm volatile("barrier.cluster.arrive.aligned;" ::: "memory");

    // Whh rows (gates r,z,n) for unit eg, k-cols [32c,32c+32), as f32x2 pairs
    unsigned long long w0[16], w1[16], w2[16];
    {
        const ulonglong2* r0 = (const ulonglong2*)(Whh + (size_t)(eg)       * 256 + c * 32);
        const ulonglong2* r1 = (const ulonglong2*)(Whh + (size_t)(256 + eg) * 256 + c * 32);
        const ulonglong2* r2 = (const ulonglong2*)(Whh + (size_t)(512 + eg) * 256 + c * 32);
#pragma unroll
        for (int q = 0; q < 8; q++) {
            ulonglong2 a = r0[q]; w0[2*q] = a.x; w0[2*q+1] = a.y;
            ulonglong2 b = r1[q]; w1[2*q] = b.x; w1[2*q+1] = b.y;
            ulonglong2 d = r2[q]; w2[2*q] = d.x; w2[2*q+1] = d.y;
        }
    }

    float bn = __ldg(bhh + 512 + eg);

    // gi gates on ALL lanes (8-lane groups share the address -> 1 request)
    float ir, iz, inn;
    {
        const float* gib = g_gi + (size_t)n * 768 + eg;   // t = 0
        ir = __ldg(gib); iz = __ldg(gib + 256); inn = __ldg(gib + 512);
    }

    // push target: peer c's hbuf slot [r*36+u]; signal peer c's mbar[r]
    unsigned dstH, dM;
    {
        unsigned hl = smem_u32_(&hbuf[0][(int)r * 36 + u]);
        unsigned ml = smem_u32_(&mbar[(int)r][0]);
        asm("mapa.shared::cluster.u32 %0, %1, %2;" : "=r"(dstH) : "r"(hl), "r"((unsigned)c));
        asm("mapa.shared::cluster.u32 %0, %1, %2;" : "=r"(dM)   : "r"(ml), "r"((unsigned)c));
    }
    // local wait target: mbar[c] (for tid<8 this is also the barrier we arm)
    const unsigned mloc = smem_u32_(&mbar[c][0]);

    asm volatile("barrier.cluster.wait.aligned;" ::: "memory");  // init visible

    for (int t = 0; t < 300; t++) {
        float hold = hbuf[t & 1][(int)r * 36 + u];
        const ulonglong2* hb = (const ulonglong2*)(&hbuf[t & 1][c * 36]);
        unsigned long long a0 = 0ULL, a1 = 0ULL, a2 = 0ULL;
#pragma unroll
        for (int q = 0; q < 8; q++) {
            ulonglong2 h2 = hb[q];
            a0 = fma2_(w0[2*q],   h2.x, a0);
            a1 = fma2_(w1[2*q],   h2.x, a1);
            a2 = fma2_(w2[2*q],   h2.x, a2);
            a0 = fma2_(w0[2*q+1], h2.y, a0);
            a1 = fma2_(w1[2*q+1], h2.y, a1);
            a2 = fma2_(w2[2*q+1], h2.y, a2);
        }
        float s0, s1, s2;
        {
            float lo, hi;
            asm("mov.b64 {%0,%1}, %2;" : "=f"(lo), "=f"(hi) : "l"(a0)); s0 = lo + hi;
            asm("mov.b64 {%0,%1}, %2;" : "=f"(lo), "=f"(hi) : "l"(a1)); s1 = lo + hi;
            asm("mov.b64 {%0,%1}, %2;" : "=f"(lo), "=f"(hi) : "l"(a2)); s2 = lo + hi;
        }
#pragma unroll
        for (int o = 4; o >= 1; o >>= 1) {
            s0 += __shfl_xor_sync(0xffffffffu, s0, o);
            s1 += __shfl_xor_sync(0xffffffffu, s1, o);
            s2 += __shfl_xor_sync(0xffffffffu, s2, o);
        }

        float rg = sigmoidf_(ir + s0);
        float zg = sigmoidf_(iz + s1);
        float ng = tanhf_(fmaf(rg, s2 + bn, inn));   // n = tanh(i_n + r*(hdot+bhh_n))
        float hnew = fmaf(zg, hold - ng, ng);

        if (t == 299) {
            if (c == 0) {
                outp[(size_t)(n * 300 + t) * 256 + eg] = hnew;
                hid[n * 256 + eg] = hnew;
            }
            break;
        }

        const unsigned boff = (unsigned)(((t + 1) & 1) * 1152);
        const unsigned moff = (unsigned)(((t + 1) & 1) * 8);

        if (tid < 8) {   // arm OWN source-barrier mbar[tid][s]: 32 msgs * 4B
            asm volatile("mbarrier.arrive.expect_tx.shared.b64 _, [%0], 128;"
                         :: "r"(mloc + moff) : "memory");
        }
        // push my unit's value to peer c; signal peer c's mbar[r][s]
        asm volatile(
            "st.async.shared::cluster.mbarrier::complete_tx::bytes.b32 [%0], %1, [%2];"
            :: "r"(dstH + boff), "r"(__float_as_uint(hnew)), "r"(dM + moff)
            : "memory");

        if (c == 0)
            outp[(size_t)(n * 300 + t) * 256 + eg] = hnew;

        // prefetch next step's gi gates (hides under the wait)
        {
            const float* gib = g_gi + (size_t)((t + 1) * 8 + n) * 768 + eg;
            ir = __ldg(gib); iz = __ldg(gib + 256); inn = __ldg(gib + 512);
        }

        // wait ONLY for my source CTA's chunk: mbar[c][s], parity (t>>1)&1
        {
            unsigned mb = mloc + moff;
            unsigned par = (unsigned)((t >> 1) & 1);
            unsigned done;
            asm volatile(
                "{\n\t.reg .pred p;\n\t"
                "mbarrier.try_wait.parity.acquire.cta.shared::cta.b64 p, [%1], %2;\n\t"
                "selp.b32 %0, 1, 0, p;\n\t}"
                : "=r"(done) : "r"(mb), "r"(par) : "memory");
            if (!done) {
                asm volatile(
                    "{\n\t.reg .pred P1;\n\t"
                    "W_%=:\n\t"
                    "mbarrier.try_wait.parity.acquire.cta.shared::cta.b64 P1, [%0], %1, 0x989680;\n\t"
                    "@P1 bra.uni D_%=;\n\t"
                    "bra.uni W_%=;\n\t"
                    "D_%=:\n\t}"
                    :: "r"(mb), "r"(par) : "memory");
            }
        }
        // HB edge for `hold`: lane r of this warp acquired mbar[r]; the warp
        // barrier publishes that acquire to all lanes before the next read.
        __syncwarp();
    }
}

// ---------------- attention: scores + softmax -------------------------------
__global__ void attn_kernel(const float* __restrict__ v, float* __restrict__ attn) {
    __shared__ float w2s[10 * 256];
    __shared__ float vs[256];
    __shared__ float red[8];

    int x = threadIdx.x;                 // 0..159
    int tb = blockIdx.x, n = blockIdx.y;
    int t0 = tb * 10;

    for (int i = x; i < 2560; i += 160)
        w2s[i] = g_w2[(size_t)(n * 300 + t0) * 256 + i];
    for (int i = x; i < 256; i += 160)
        vs[i] = v[i];
    __syncthreads();

    float S;
    {
        float s0 = 0.f, s1 = 0.f, s2 = 0.f, s3 = 0.f;
        for (int e = 0; e < 256; e += 4) {
            s0 += vs[e]; s1 += vs[e + 1]; s2 += vs[e + 2]; s3 += vs[e + 3];
        }
        S = (s0 + s1) + (s2 + s3);
    }

    float acc[10];
#pragma unroll
    for (int tt = 0; tt < 10; tt++) acc[tt] = 0.f;

    const float4* urow = (const float4*)(g_u2 + (size_t)(n * 160 + x) * 256);
    for (int e4 = 0; e4 < 64; e4++) {
        float4 u4 = __ldg(urow + e4);
#pragma unroll
        for (int j = 0; j < 4; j++) {
            float ue = (j == 0) ? u4.x : (j == 1) ? u4.y : (j == 2) ? u4.z : u4.w;
            int e = e4 * 4 + j;
            float ve = vs[e];
#pragma unroll
            for (int tt = 0; tt < 10; tt++) {
                float a = w2s[tt * 256 + e] + ue;      // already * 2*log2e
                float r = rcpf_(1.f + ex2f_(a));       // tanh = 1 - 2r
                acc[tt] = fmaf(ve, r, acc[tt]);
            }
        }
    }

    int lane = x & 31, wid = x >> 5;
    for (int tt = 0; tt < 10; tt++) {
        float sc = fmaf(-2.f, acc[tt], S);
        float m = sc;
#pragma unroll
        for (int o = 16; o > 0; o >>= 1)
            m = fmaxf(m, __shfl_xor_sync(0xffffffffu, m, o));
        if (lane == 0) red[wid] = m;
        __syncthreads();
        m = fmaxf(fmaxf(fmaxf(red[0], red[1]), fmaxf(red[2], red[3])), red[4]);

        float p = ex2f_((sc - m) * LOG2E);
        float s = p;
#pragma unroll
        for (int o = 16; o > 0; o >>= 1)
            s += __shfl_xor_sync(0xffffffffu, s, o);
        __syncthreads();
        if (lane == 0) red[wid] = s;
        __syncthreads();
        s = ((red[0] + red[1]) + (red[2] + red[3])) + red[4];

        attn[(size_t)(n * 300 + t0 + tt) * 160 + x] = p * rcpf_(s);
        __syncthreads();
    }
}

// ---------------- launcher ---------------------------------------------------
extern "C" void kernel_launch(void* const* d_in, const int* in_sizes, int n_in,
                              void* d_out, int out_size) {
    (void)in_sizes; (void)n_in; (void)out_size;
    const float* inputs = (const float*)d_in[0];
    const float* memory = (const float*)d_in[1];
    const float* h0     = (const float*)d_in[2];
    const float* Wih    = (const float*)d_in[3];
    const float* Whh    = (const float*)d_in[4];
    const float* bih    = (const float*)d_in[5];
    const float* bhh    = (const float*)d_in[6];
    const float* W      = (const float*)d_in[7];
    const float* U      = (const float*)d_in[8];
    const float* v      = (const float*)d_in[9];

    float* out     = (float*)d_out;
    float* attn    = out;                 // [8,300,160] = 384000
    float* outputs = out + 384000;        // [8,300,256] = 614400
    float* hidden  = out + 998400;        // [1,8,256]   = 2048

    gi_kernel<<<dim3(150, 3), 256>>>(inputs, Wih, bih, bhh);
    u_kernel<<<80, 256>>>(memory, U);
    probe_kernel<<<1, 32>>>();            // keeps gru at profiled launch slot
    gru_kernel<<<64, 256>>>(h0, Whh, bhh, outputs, hidden);
    w_kernel<<<150, 256>>>(outputs, W);
    attn_kernel<<<dim3(30, 8), 160>>>(v, attn);
}

// round 16
// speedup vs baseline: 1.1848x; 1.1848x over previous
#include <cuda_runtime.h>
#include <cstdint>

#define LOG2E     1.4426950408889634f
#define TWO_LOG2E 2.8853900817779268f

// ---------------- scratch (device globals: no allocation allowed) ----------
__device__ float g_gi[2400 * 768];   // pre-GRU input gates  [t*8+n][768]
__device__ float g_u2[1280 * 256];   // 2*log2e * (memory @ U^T)  [n*160+x][256]
__device__ float g_w2[2400 * 256];   // 2*log2e * (outputs @ W^T) [n*300+t][256]

// ---------------- fast math ------------------------------------------------
__device__ __forceinline__ float ex2f_(float x) {
    float y; asm("ex2.approx.f32 %0, %1;" : "=f"(y) : "f"(x)); return y;
}
__device__ __forceinline__ float rcpf_(float x) {
    float y; asm("rcp.approx.f32 %0, %1;" : "=f"(y) : "f"(x)); return y;
}
__device__ __forceinline__ float sigmoidf_(float x) {
    return rcpf_(1.f + ex2f_(-x * LOG2E));
}
__device__ __forceinline__ float tanhf_(float x) {
    return fmaf(-2.f, rcpf_(1.f + ex2f_(x * TWO_LOG2E)), 1.f);
}
__device__ __forceinline__ unsigned smem_u32_(const void* p) {
    unsigned a;
    asm("{ .reg .u64 t; cvta.to.shared.u64 t, %1; cvt.u32.u64 %0, t; }"
        : "=r"(a) : "l"(p));
    return a;
}
__device__ __forceinline__ unsigned long long fma2_(unsigned long long a,
                                                    unsigned long long b,
                                                    unsigned long long c) {
    unsigned long long d;
    asm("fma.rn.f32x2 %0, %1, %2, %3;" : "=l"(d) : "l"(a), "l"(b), "l"(c));
    return d;
}

// ---------------- kernel A: gi = inputs @ Wih^T + bih (+bhh for r,z) -------
__global__ void gi_kernel(const float* __restrict__ inp,
                          const float* __restrict__ Wih,
                          const float* __restrict__ bih,
                          const float* __restrict__ bhh) {
    __shared__ float xs[16][128];
    int tid = threadIdx.x;
    int ib = blockIdx.x, jb = blockIdx.y;
    int j = jb * 256 + tid;

    for (int q = 0; q < 2; q++) {
        int f4 = tid + 256 * q;
        int ii = f4 >> 5, pos = f4 & 31;
        int i = ib * 16 + ii;
        int t = i >> 3, n = i & 7;
        ((float4*)xs[ii])[pos] = ((const float4*)(inp + (n * 300 + t) * 128))[pos];
    }
    __syncthreads();

    float acc[16];
#pragma unroll
    for (int ii = 0; ii < 16; ii++) acc[ii] = 0.f;

    const float4* wr = (const float4*)(Wih + (size_t)j * 128);
    for (int k4 = 0; k4 < 32; k4++) {
        float4 w4 = __ldg(wr + k4);
#pragma unroll
        for (int ii = 0; ii < 16; ii++) {
            float4 xv = ((const float4*)xs[ii])[k4];
            acc[ii] = fmaf(w4.x, xv.x, acc[ii]);
            acc[ii] = fmaf(w4.y, xv.y, acc[ii]);
            acc[ii] = fmaf(w4.z, xv.z, acc[ii]);
            acc[ii] = fmaf(w4.w, xv.w, acc[ii]);
        }
    }
    float b = bih[j] + (jb < 2 ? bhh[j] : 0.f);
#pragma unroll
    for (int ii = 0; ii < 16; ii++)
        g_gi[(size_t)(ib * 16 + ii) * 768 + j] = acc[ii] + b;
}

// ---------------- shared 256-K GEMM body (R12 version — measured best) -----
__device__ __forceinline__ void gemm256_body(const float* __restrict__ A,
                                             const float* __restrict__ B,
                                             float* __restrict__ out,
                                             float scale) {
    __shared__ float xs[16][256];
    int tid = threadIdx.x, ib = blockIdx.x;
    for (int q = 0; q < 4; q++) {
        int f4 = tid + 256 * q;
        int ii = f4 >> 6, pos = f4 & 63;
        ((float4*)xs[ii])[pos] = ((const float4*)(A + (size_t)(ib * 16 + ii) * 256))[pos];
    }
    __syncthreads();

    float acc[16];
#pragma unroll
    for (int ii = 0; ii < 16; ii++) acc[ii] = 0.f;

    const float4* br = (const float4*)(B + (size_t)tid * 256);
    for (int k4 = 0; k4 < 64; k4++) {
        float4 b4 = __ldg(br + k4);
#pragma unroll
        for (int ii = 0; ii < 16; ii++) {
            float4 xv = ((const float4*)xs[ii])[k4];
            acc[ii] = fmaf(b4.x, xv.x, acc[ii]);
            acc[ii] = fmaf(b4.y, xv.y, acc[ii]);
            acc[ii] = fmaf(b4.z, xv.z, acc[ii]);
            acc[ii] = fmaf(b4.w, xv.w, acc[ii]);
        }
    }
#pragma unroll
    for (int ii = 0; ii < 16; ii++)
        out[(size_t)(ib * 16 + ii) * 256 + tid] = scale * acc[ii];
}

__global__ void u_kernel(const float* __restrict__ mem, const float* __restrict__ U) {
    gemm256_body(mem, U, g_u2, TWO_LOG2E);
}
__global__ void w_kernel(const float* __restrict__ outp, const float* __restrict__ W) {
    gemm256_body(outp, W, g_w2, TWO_LOG2E);
}

// ---------------- profiling alignment no-op (gru stays launch idx 3) -------
__global__ void probe_kernel() {}

// ---------------- GRU (R13 version — measured best: 202us) -----------------
// 8-CTA cluster per batch; single tx-mbarrier per slot; lane fan-out st.async
// (1 push per thread); padded hbuf (36-float chunk stride, conflict-free);
// gi gates loaded on ALL lanes (broadcast __ldg, prefetched under the wait);
// hold hoisted to loop top.
__global__ void __launch_bounds__(256, 1) __cluster_dims__(8, 1, 1)
gru_kernel(const float* __restrict__ h0, const float* __restrict__ Whh,
           const float* __restrict__ bhh,
           float* __restrict__ outp, float* __restrict__ hid) {
    __shared__ __align__(16) float hbuf[2][288];          // 8 chunks x 36 floats
    __shared__ __align__(8)  unsigned long long mbar[2];

    int tid = threadIdx.x;
    int n = blockIdx.x >> 3;
    unsigned r;
    asm("mov.u32 %0, %%cluster_ctarank;" : "=r"(r));
    int u = tid >> 3, c = tid & 7;
    const int eg = 32 * (int)r + u;

    if (tid == 0) {
        unsigned m0 = smem_u32_(&mbar[0]);
        asm volatile("mbarrier.init.shared.b64 [%0], 1;" :: "r"(m0) : "memory");
        asm volatile("mbarrier.init.shared.b64 [%0], 1;" :: "r"(m0 + 8) : "memory");
    }
    hbuf[0][(tid >> 5) * 36 + (tid & 31)] = h0[n * 256 + tid];
    __syncthreads();
    asm volatile("barrier.cluster.arrive.aligned;" ::: "memory");

    // Whh rows (gates r,z,n) for unit eg, k-cols [32c,32c+32), as f32x2 pairs
    unsigned long long w0[16], w1[16], w2[16];
    {
        const ulonglong2* r0 = (const ulonglong2*)(Whh + (size_t)(eg)       * 256 + c * 32);
        const ulonglong2* r1 = (const ulonglong2*)(Whh + (size_t)(256 + eg) * 256 + c * 32);
        const ulonglong2* r2 = (const ulonglong2*)(Whh + (size_t)(512 + eg) * 256 + c * 32);
#pragma unroll
        for (int q = 0; q < 8; q++) {
            ulonglong2 a = r0[q]; w0[2*q] = a.x; w0[2*q+1] = a.y;
            ulonglong2 b = r1[q]; w1[2*q] = b.x; w1[2*q+1] = b.y;
            ulonglong2 d = r2[q]; w2[2*q] = d.x; w2[2*q+1] = d.y;
        }
    }

    float bn = __ldg(bhh + 512 + eg);

    // gi gates on ALL lanes (8-lane groups share the address -> broadcast)
    float ir, iz, inn;
    {
        const float* gib = g_gi + (size_t)n * 768 + eg;   // t = 0
        ir = __ldg(gib); iz = __ldg(gib + 256); inn = __ldg(gib + 512);
    }

    // each thread pushes unit eg's value to peer c's padded slot; signal mbar
    unsigned dstH, dM;
    {
        unsigned hl = smem_u32_(&hbuf[0][(int)r * 36 + u]);
        unsigned m0 = smem_u32_(&mbar[0]);
        asm("mapa.shared::cluster.u32 %0, %1, %2;" : "=r"(dstH) : "r"(hl), "r"((unsigned)c));
        asm("mapa.shared::cluster.u32 %0, %1, %2;" : "=r"(dM)   : "r"(m0), "r"((unsigned)c));
    }
    const unsigned mloc = smem_u32_(&mbar[0]);

    asm volatile("barrier.cluster.wait.aligned;" ::: "memory");  // init visible

    for (int t = 0; t < 300; t++) {
        float hold = hbuf[t & 1][(int)r * 36 + u];       // hoisted off epilogue
        const ulonglong2* hb = (const ulonglong2*)(&hbuf[t & 1][c * 36]);
        unsigned long long a0 = 0ULL, a1 = 0ULL, a2 = 0ULL;
#pragma unroll
        for (int q = 0; q < 8; q++) {
            ulonglong2 h2 = hb[q];
            a0 = fma2_(w0[2*q],   h2.x, a0);
            a1 = fma2_(w1[2*q],   h2.x, a1);
            a2 = fma2_(w2[2*q],   h2.x, a2);
            a0 = fma2_(w0[2*q+1], h2.y, a0);
            a1 = fma2_(w1[2*q+1], h2.y, a1);
            a2 = fma2_(w2[2*q+1], h2.y, a2);
        }
        float s0, s1, s2;
        {
            float lo, hi;
            asm("mov.b64 {%0,%1}, %2;" : "=f"(lo), "=f"(hi) : "l"(a0)); s0 = lo + hi;
            asm("mov.b64 {%0,%1}, %2;" : "=f"(lo), "=f"(hi) : "l"(a1)); s1 = lo + hi;
            asm("mov.b64 {%0,%1}, %2;" : "=f"(lo), "=f"(hi) : "l"(a2)); s2 = lo + hi;
        }
#pragma unroll
        for (int o = 4; o >= 1; o >>= 1) {
            s0 += __shfl_xor_sync(0xffffffffu, s0, o);
            s1 += __shfl_xor_sync(0xffffffffu, s1, o);
            s2 += __shfl_xor_sync(0xffffffffu, s2, o);
        }

        // epilogue on ALL lanes (gi gates already local; no shfl on the path)
        float rg = sigmoidf_(ir + s0);
        float zg = sigmoidf_(iz + s1);
        float ng = tanhf_(fmaf(rg, s2 + bn, inn));       // n = tanh(i_n + r*(hdot+bhh_n))
        float hnew = fmaf(zg, hold - ng, ng);

        if (t == 299) {
            if (c == 0) {
                outp[(size_t)(n * 300 + t) * 256 + eg] = hnew;
                hid[n * 256 + eg] = hnew;
            }
            break;
        }

        const unsigned boff = (unsigned)(((t + 1) & 1) * 1152);
        const unsigned moff = (unsigned)(((t + 1) & 1) * 8);

        if (tid == 0) {   // arm local barrier for b_{t+1}: 256 msgs * 4B
            asm volatile("mbarrier.arrive.expect_tx.shared.b64 _, [%0], 1024;"
                         :: "r"(mloc + moff) : "memory");
        }
        // EVERY thread pushes one 4B value to its peer (fan-out 1)
        asm volatile(
            "st.async.shared::cluster.mbarrier::complete_tx::bytes.b32 [%0], %1, [%2];"
            :: "r"(dstH + boff), "r"(__float_as_uint(hnew)), "r"(dM + moff)
            : "memory");

        if (c == 0)
            outp[(size_t)(n * 300 + t) * 256 + eg] = hnew;

        // prefetch next step's gi gates on ALL lanes (hides under the wait)
        {
            const float* gib = g_gi + (size_t)((t + 1) * 8 + n) * 768 + eg;
            ir = __ldg(gib); iz = __ldg(gib + 256); inn = __ldg(gib + 512);
        }

        // wait for b_{t+1} on LOCAL mbarrier; parity = (t>>1)&1
        {
            unsigned mb = mloc + moff;
            unsigned par = (unsigned)((t >> 1) & 1);
            unsigned done;
            asm volatile(
                "{\n\t.reg .pred p;\n\t"
                "mbarrier.try_wait.parity.acquire.cta.shared::cta.b64 p, [%1], %2;\n\t"
                "selp.b32 %0, 1, 0, p;\n\t}"
                : "=r"(done) : "r"(mb), "r"(par) : "memory");
            if (!done) {
                asm volatile(
                    "{\n\t.reg .pred P1;\n\t"
                    "W_%=:\n\t"
                    "mbarrier.try_wait.parity.acquire.cta.shared::cta.b64 P1, [%0], %1, 0x989680;\n\t"
                    "@P1 bra.uni D_%=;\n\t"
                    "bra.uni W_%=;\n\t"
                    "D_%=:\n\t}"
                    :: "r"(mb), "r"(par) : "memory");
            }
        }
    }
}

// ---------------- attention: scores + softmax -------------------------------
__global__ void attn_kernel(const float* __restrict__ v, float* __restrict__ attn) {
    __shared__ float w2s[10 * 256];
    __shared__ float vs[256];
    __shared__ float red[8];

    int x = threadIdx.x;                 // 0..159
    int tb = blockIdx.x, n = blockIdx.y;
    int t0 = tb * 10;

    for (int i = x; i < 2560; i += 160)
        w2s[i] = g_w2[(size_t)(n * 300 + t0) * 256 + i];
    for (int i = x; i < 256; i += 160)
        vs[i] = v[i];
    __syncthreads();

    float S;
    {
        float s0 = 0.f, s1 = 0.f, s2 = 0.f, s3 = 0.f;
        for (int e = 0; e < 256; e += 4) {
            s0 += vs[e]; s1 += vs[e + 1]; s2 += vs[e + 2]; s3 += vs[e + 3];
        }
        S = (s0 + s1) + (s2 + s3);
    }

    float acc[10];
#pragma unroll
    for (int tt = 0; tt < 10; tt++) acc[tt] = 0.f;

    const float4* urow = (const float4*)(g_u2 + (size_t)(n * 160 + x) * 256);
    for (int e4 = 0; e4 < 64; e4++) {
        float4 u4 = __ldg(urow + e4);
#pragma unroll
        for (int j = 0; j < 4; j++) {
            float ue = (j == 0) ? u4.x : (j == 1) ? u4.y : (j == 2) ? u4.z : u4.w;
            int e = e4 * 4 + j;
            float ve = vs[e];
#pragma unroll
            for (int tt = 0; tt < 10; tt++) {
                float a = w2s[tt * 256 + e] + ue;      // already * 2*log2e
                float r = rcpf_(1.f + ex2f_(a));       // tanh = 1 - 2r
                acc[tt] = fmaf(ve, r, acc[tt]);
            }
        }
    }

    int lane = x & 31, wid = x >> 5;
    for (int tt = 0; tt < 10; tt++) {
        float sc = fmaf(-2.f, acc[tt], S);
        float m = sc;
#pragma unroll
        for (int o = 16; o > 0; o >>= 1)
            m = fmaxf(m, __shfl_xor_sync(0xffffffffu, m, o));
        if (lane == 0) red[wid] = m;
        __syncthreads();
        m = fmaxf(fmaxf(fmaxf(red[0], red[1]), fmaxf(red[2], red[3])), red[4]);

        float p = ex2f_((sc - m) * LOG2E);
        float s = p;
#pragma unroll
        for (int o = 16; o > 0; o >>= 1)
            s += __shfl_xor_sync(0xffffffffu, s, o);
        __syncthreads();
        if (lane == 0) red[wid] = s;
        __syncthreads();
        s = ((red[0] + red[1]) + (red[2] + red[3])) + red[4];

        attn[(size_t)(n * 300 + t0 + tt) * 160 + x] = p * rcpf_(s);
        __syncthreads();
    }
}

// ---------------- launcher ---------------------------------------------------
extern "C" void kernel_launch(void* const* d_in, const int* in_sizes, int n_in,
                              void* d_out, int out_size) {
    (void)in_sizes; (void)n_in; (void)out_size;
    const float* inputs = (const float*)d_in[0];
    const float* memory = (const float*)d_in[1];
    const float* h0     = (const float*)d_in[2];
    const float* Wih    = (const float*)d_in[3];
    const float* Whh    = (const float*)d_in[4];
    const float* bih    = (const float*)d_in[5];
    const float* bhh    = (const float*)d_in[6];
    const float* W      = (const float*)d_in[7];
    const float* U      = (const float*)d_in[8];
    const float* v      = (const float*)d_in[9];

    float* out     = (float*)d_out;
    float* attn    = out;                 // [8,300,160] = 384000
    float* outputs = out + 384000;        // [8,300,256] = 614400
    float* hidden  = out + 998400;        // [1,8,256]   = 2048

    gi_kernel<<<dim3(150, 3), 256>>>(inputs, Wih, bih, bhh);
    u_kernel<<<80, 256>>>(memory, U);
    probe_kernel<<<1, 32>>>();            // keeps gru at profiled launch slot
    gru_kernel<<<64, 256>>>(h0, Whh, bhh, outputs, hidden);
    w_kernel<<<150, 256>>>(outputs, W);
    attn_kernel<<<dim3(30, 8), 160>>>(v, attn);
}

// round 17
// speedup vs baseline: 1.3178x; 1.1123x over previous
#include <cuda_runtime.h>
#include <cstdint>

#define LOG2E     1.4426950408889634f
#define TWO_LOG2E 2.8853900817779268f

// ---------------- scratch (device globals: no allocation allowed) ----------
__device__ float g_gi[2400 * 768];   // pre-GRU input gates  [t*8+n][768]
__device__ float g_u2[1280 * 256];   // memory @ U^T   [n*160+x][256] (unscaled)
__device__ float g_w2[2400 * 256];   // outputs @ W^T  [n*300+t][256] (unscaled)

// ---------------- fast math ------------------------------------------------
__device__ __forceinline__ float ex2f_(float x) {
    float y; asm("ex2.approx.f32 %0, %1;" : "=f"(y) : "f"(x)); return y;
}
__device__ __forceinline__ float rcpf_(float x) {
    float y; asm("rcp.approx.f32 %0, %1;" : "=f"(y) : "f"(x)); return y;
}
__device__ __forceinline__ float tanha_(float x) {     // single MUFU.TANH
    float y; asm("tanh.approx.f32 %0, %1;" : "=f"(y) : "f"(x)); return y;
}
__device__ __forceinline__ float sigmoidf_(float x) {
    return rcpf_(1.f + ex2f_(-x * LOG2E));
}
__device__ __forceinline__ float tanhf_(float x) {     // accurate 2-MUFU form (GRU)
    return fmaf(-2.f, rcpf_(1.f + ex2f_(x * TWO_LOG2E)), 1.f);
}
__device__ __forceinline__ unsigned smem_u32_(const void* p) {
    unsigned a;
    asm("{ .reg .u64 t; cvta.to.shared.u64 t, %1; cvt.u32.u64 %0, t; }"
        : "=r"(a) : "l"(p));
    return a;
}
__device__ __forceinline__ unsigned long long fma2_(unsigned long long a,
                                                    unsigned long long b,
                                                    unsigned long long c) {
    unsigned long long d;
    asm("fma.rn.f32x2 %0, %1, %2, %3;" : "=l"(d) : "l"(a), "l"(b), "l"(c));
    return d;
}

// ---------------- kernel A: gi = inputs @ Wih^T + bih (+bhh for r,z) -------
__global__ void gi_kernel(const float* __restrict__ inp,
                          const float* __restrict__ Wih,
                          const float* __restrict__ bih,
                          const float* __restrict__ bhh) {
    __shared__ float xs[16][128];
    int tid = threadIdx.x;
    int ib = blockIdx.x, jb = blockIdx.y;
    int j = jb * 256 + tid;

    for (int q = 0; q < 2; q++) {
        int f4 = tid + 256 * q;
        int ii = f4 >> 5, pos = f4 & 31;
        int i = ib * 16 + ii;
        int t = i >> 3, n = i & 7;
        ((float4*)xs[ii])[pos] = ((const float4*)(inp + (n * 300 + t) * 128))[pos];
    }
    __syncthreads();

    float acc[16];
#pragma unroll
    for (int ii = 0; ii < 16; ii++) acc[ii] = 0.f;

    const float4* wr = (const float4*)(Wih + (size_t)j * 128);
    for (int k4 = 0; k4 < 32; k4++) {
        float4 w4 = __ldg(wr + k4);
#pragma unroll
        for (int ii = 0; ii < 16; ii++) {
            float4 xv = ((const float4*)xs[ii])[k4];
            acc[ii] = fmaf(w4.x, xv.x, acc[ii]);
            acc[ii] = fmaf(w4.y, xv.y, acc[ii]);
            acc[ii] = fmaf(w4.z, xv.z, acc[ii]);
            acc[ii] = fmaf(w4.w, xv.w, acc[ii]);
        }
    }
    float b = bih[j] + (jb < 2 ? bhh[j] : 0.f);
#pragma unroll
    for (int ii = 0; ii < 16; ii++)
        g_gi[(size_t)(ib * 16 + ii) * 768 + j] = acc[ii] + b;
}

// ---------------- shared 256-K GEMM body (R12 version — measured best) -----
__device__ __forceinline__ void gemm256_body(const float* __restrict__ A,
                                             const float* __restrict__ B,
                                             float* __restrict__ out,
                                             float scale) {
    __shared__ float xs[16][256];
    int tid = threadIdx.x, ib = blockIdx.x;
    for (int q = 0; q < 4; q++) {
        int f4 = tid + 256 * q;
        int ii = f4 >> 6, pos = f4 & 63;
        ((float4*)xs[ii])[pos] = ((const float4*)(A + (size_t)(ib * 16 + ii) * 256))[pos];
    }
    __syncthreads();

    float acc[16];
#pragma unroll
    for (int ii = 0; ii < 16; ii++) acc[ii] = 0.f;

    const float4* br = (const float4*)(B + (size_t)tid * 256);
    for (int k4 = 0; k4 < 64; k4++) {
        float4 b4 = __ldg(br + k4);
#pragma unroll
        for (int ii = 0; ii < 16; ii++) {
            float4 xv = ((const float4*)xs[ii])[k4];
            acc[ii] = fmaf(b4.x, xv.x, acc[ii]);
            acc[ii] = fmaf(b4.y, xv.y, acc[ii]);
            acc[ii] = fmaf(b4.z, xv.z, acc[ii]);
            acc[ii] = fmaf(b4.w, xv.w, acc[ii]);
        }
    }
#pragma unroll
    for (int ii = 0; ii < 16; ii++)
        out[(size_t)(ib * 16 + ii) * 256 + tid] = scale * acc[ii];
}

__global__ void u_kernel(const float* __restrict__ mem, const float* __restrict__ U) {
    gemm256_body(mem, U, g_u2, 1.0f);     // unscaled: tanh.approx takes raw arg
}
__global__ void w_kernel(const float* __restrict__ outp, const float* __restrict__ W) {
    gemm256_body(outp, W, g_w2, 1.0f);
}

// ---------------- profiling alignment no-op (gru stays launch idx 3) -------
__global__ void probe_kernel() {}

// ---------------- GRU (R13 version — measured best: 202us) -----------------
__global__ void __launch_bounds__(256, 1) __cluster_dims__(8, 1, 1)
gru_kernel(const float* __restrict__ h0, const float* __restrict__ Whh,
           const float* __restrict__ bhh,
           float* __restrict__ outp, float* __restrict__ hid) {
    __shared__ __align__(16) float hbuf[2][288];          // 8 chunks x 36 floats
    __shared__ __align__(8)  unsigned long long mbar[2];

    int tid = threadIdx.x;
    int n = blockIdx.x >> 3;
    unsigned r;
    asm("mov.u32 %0, %%cluster_ctarank;" : "=r"(r));
    int u = tid >> 3, c = tid & 7;
    const int eg = 32 * (int)r + u;

    if (tid == 0) {
        unsigned m0 = smem_u32_(&mbar[0]);
        asm volatile("mbarrier.init.shared.b64 [%0], 1;" :: "r"(m0) : "memory");
        asm volatile("mbarrier.init.shared.b64 [%0], 1;" :: "r"(m0 + 8) : "memory");
    }
    hbuf[0][(tid >> 5) * 36 + (tid & 31)] = h0[n * 256 + tid];
    __syncthreads();
    asm volatile("barrier.cluster.arrive.aligned;" ::: "memory");

    unsigned long long w0[16], w1[16], w2[16];
    {
        const ulonglong2* r0 = (const ulonglong2*)(Whh + (size_t)(eg)       * 256 + c * 32);
        const ulonglong2* r1 = (const ulonglong2*)(Whh + (size_t)(256 + eg) * 256 + c * 32);
        const ulonglong2* r2 = (const ulonglong2*)(Whh + (size_t)(512 + eg) * 256 + c * 32);
#pragma unroll
        for (int q = 0; q < 8; q++) {
            ulonglong2 a = r0[q]; w0[2*q] = a.x; w0[2*q+1] = a.y;
            ulonglong2 b = r1[q]; w1[2*q] = b.x; w1[2*q+1] = b.y;
            ulonglong2 d = r2[q]; w2[2*q] = d.x; w2[2*q+1] = d.y;
        }
    }

    float bn = __ldg(bhh + 512 + eg);

    float ir, iz, inn;
    {
        const float* gib = g_gi + (size_t)n * 768 + eg;   // t = 0
        ir = __ldg(gib); iz = __ldg(gib + 256); inn = __ldg(gib + 512);
    }

    unsigned dstH, dM;
    {
        unsigned hl = smem_u32_(&hbuf[0][(int)r * 36 + u]);
        unsigned m0 = smem_u32_(&mbar[0]);
        asm("mapa.shared::cluster.u32 %0, %1, %2;" : "=r"(dstH) : "r"(hl), "r"((unsigned)c));
        asm("mapa.shared::cluster.u32 %0, %1, %2;" : "=r"(dM)   : "r"(m0), "r"((unsigned)c));
    }
    const unsigned mloc = smem_u32_(&mbar[0]);

    asm volatile("barrier.cluster.wait.aligned;" ::: "memory");  // init visible

    for (int t = 0; t < 300; t++) {
        float hold = hbuf[t & 1][(int)r * 36 + u];
        const ulonglong2* hb = (const ulonglong2*)(&hbuf[t & 1][c * 36]);
        unsigned long long a0 = 0ULL, a1 = 0ULL, a2 = 0ULL;
#pragma unroll
        for (int q = 0; q < 8; q++) {
            ulonglong2 h2 = hb[q];
            a0 = fma2_(w0[2*q],   h2.x, a0);
            a1 = fma2_(w1[2*q],   h2.x, a1);
            a2 = fma2_(w2[2*q],   h2.x, a2);
            a0 = fma2_(w0[2*q+1], h2.y, a0);
            a1 = fma2_(w1[2*q+1], h2.y, a1);
            a2 = fma2_(w2[2*q+1], h2.y, a2);
        }
        float s0, s1, s2;
        {
            float lo, hi;
            asm("mov.b64 {%0,%1}, %2;" : "=f"(lo), "=f"(hi) : "l"(a0)); s0 = lo + hi;
            asm("mov.b64 {%0,%1}, %2;" : "=f"(lo), "=f"(hi) : "l"(a1)); s1 = lo + hi;
            asm("mov.b64 {%0,%1}, %2;" : "=f"(lo), "=f"(hi) : "l"(a2)); s2 = lo + hi;
        }
#pragma unroll
        for (int o = 4; o >= 1; o >>= 1) {
            s0 += __shfl_xor_sync(0xffffffffu, s0, o);
            s1 += __shfl_xor_sync(0xffffffffu, s1, o);
            s2 += __shfl_xor_sync(0xffffffffu, s2, o);
        }

        float rg = sigmoidf_(ir + s0);
        float zg = sigmoidf_(iz + s1);
        float ng = tanhf_(fmaf(rg, s2 + bn, inn));       // accurate form (compounds)
        float hnew = fmaf(zg, hold - ng, ng);

        if (t == 299) {
            if (c == 0) {
                outp[(size_t)(n * 300 + t) * 256 + eg] = hnew;
                hid[n * 256 + eg] = hnew;
            }
            break;
        }

        const unsigned boff = (unsigned)(((t + 1) & 1) * 1152);
        const unsigned moff = (unsigned)(((t + 1) & 1) * 8);

        if (tid == 0) {
            asm volatile("mbarrier.arrive.expect_tx.shared.b64 _, [%0], 1024;"
                         :: "r"(mloc + moff) : "memory");
        }
        asm volatile(
            "st.async.shared::cluster.mbarrier::complete_tx::bytes.b32 [%0], %1, [%2];"
            :: "r"(dstH + boff), "r"(__float_as_uint(hnew)), "r"(dM + moff)
            : "memory");

        if (c == 0)
            outp[(size_t)(n * 300 + t) * 256 + eg] = hnew;

        {
            const float* gib = g_gi + (size_t)((t + 1) * 8 + n) * 768 + eg;
            ir = __ldg(gib); iz = __ldg(gib + 256); inn = __ldg(gib + 512);
        }

        {
            unsigned mb = mloc + moff;
            unsigned par = (unsigned)((t >> 1) & 1);
            unsigned done;
            asm volatile(
                "{\n\t.reg .pred p;\n\t"
                "mbarrier.try_wait.parity.acquire.cta.shared::cta.b64 p, [%1], %2;\n\t"
                "selp.b32 %0, 1, 0, p;\n\t}"
                : "=r"(done) : "r"(mb), "r"(par) : "memory");
            if (!done) {
                asm volatile(
                    "{\n\t.reg .pred P1;\n\t"
                    "W_%=:\n\t"
                    "mbarrier.try_wait.parity.acquire.cta.shared::cta.b64 P1, [%0], %1, 0x989680;\n\t"
                    "@P1 bra.uni D_%=;\n\t"
                    "bra.uni W_%=;\n\t"
                    "D_%=:\n\t}"
                    :: "r"(mb), "r"(par) : "memory");
            }
        }
    }
}

// ---------------- attention: scores + softmax (1-MUFU tanh.approx) ---------
// score = sum_e v_e * tanh(w_e + u_e); inner loop = FADD + MUFU.TANH + FFMA.
__global__ void attn_kernel(const float* __restrict__ v, float* __restrict__ attn) {
    __shared__ float w2s[10 * 256];
    __shared__ float vs[256];
    __shared__ float red[8];

    int x = threadIdx.x;                 // 0..159
    int tb = blockIdx.x, n = blockIdx.y;
    int t0 = tb * 10;

    for (int i = x; i < 2560; i += 160)
        w2s[i] = g_w2[(size_t)(n * 300 + t0) * 256 + i];
    for (int i = x; i < 256; i += 160)
        vs[i] = v[i];
    __syncthreads();

    float acc[10];
#pragma unroll
    for (int tt = 0; tt < 10; tt++) acc[tt] = 0.f;

    const float4* urow = (const float4*)(g_u2 + (size_t)(n * 160 + x) * 256);
    for (int e4 = 0; e4 < 64; e4++) {
        float4 u4 = __ldg(urow + e4);
#pragma unroll
        for (int j = 0; j < 4; j++) {
            float ue = (j == 0) ? u4.x : (j == 1) ? u4.y : (j == 2) ? u4.z : u4.w;
            int e = e4 * 4 + j;
            float ve = vs[e];
#pragma unroll
            for (int tt = 0; tt < 10; tt++) {
                float th = tanha_(w2s[tt * 256 + e] + ue);   // 1 MUFU
                acc[tt] = fmaf(ve, th, acc[tt]);
            }
        }
    }

    int lane = x & 31, wid = x >> 5;
    for (int tt = 0; tt < 10; tt++) {
        float sc = acc[tt];
        float m = sc;
#pragma unroll
        for (int o = 16; o > 0; o >>= 1)
            m = fmaxf(m, __shfl_xor_sync(0xffffffffu, m, o));
        if (lane == 0) red[wid] = m;
        __syncthreads();
        m = fmaxf(fmaxf(fmaxf(red[0], red[1]), fmaxf(red[2], red[3])), red[4]);

        float p = ex2f_((sc - m) * LOG2E);
        float s = p;
#pragma unroll
        for (int o = 16; o > 0; o >>= 1)
            s += __shfl_xor_sync(0xffffffffu, s, o);
        __syncthreads();
        if (lane == 0) red[wid] = s;
        __syncthreads();
        s = ((red[0] + red[1]) + (red[2] + red[3])) + red[4];

        attn[(size_t)(n * 300 + t0 + tt) * 160 + x] = p * rcpf_(s);
        __syncthreads();
    }
}

// ---------------- launcher ---------------------------------------------------
extern "C" void kernel_launch(void* const* d_in, const int* in_sizes, int n_in,
                              void* d_out, int out_size) {
    (void)in_sizes; (void)n_in; (void)out_size;
    const float* inputs = (const float*)d_in[0];
    const float* memory = (const float*)d_in[1];
    const float* h0     = (const float*)d_in[2];
    const float* Wih    = (const float*)d_in[3];
    const float* Whh    = (const float*)d_in[4];
    const float* bih    = (const float*)d_in[5];
    const float* bhh    = (const float*)d_in[6];
    const float* W      = (const float*)d_in[7];
    const float* U      = (const float*)d_in[8];
    const float* v      = (const float*)d_in[9];

    float* out     = (float*)d_out;
    float* attn    = out;                 // [8,300,160] = 384000
    float* outputs = out + 384000;        // [8,300,256] = 614400
    float* hidden  = out + 998400;        // [1,8,256]   = 2048

    gi_kernel<<<dim3(150, 3), 256>>>(inputs, Wih, bih, bhh);
    u_kernel<<<80, 256>>>(memory, U);
    probe_kernel<<<1, 32>>>();            // keeps gru at profiled launch slot
    gru_kernel<<<64, 256>>>(h0, Whh, bhh, outputs, hidden);
    w_kernel<<<150, 256>>>(outputs, W);
    attn_kernel<<<dim3(30, 8), 160>>>(v, attn);
}